// round 2
// baseline (speedup 1.0000x reference)
#include <cuda_runtime.h>
#include <cstdint>
#include <cstddef>

#define B_ 8
#define T_ 256
#define V_ 32000
#define E_ 256
#define H_ 512

#define RNN_CTAS 32
#define WT_STRIDE 516                      // 512 + pad(4) for reduced bank conflicts
#define RNN_SMEM ((16*WT_STRIDE + B_*H_) * 4)

// Scratch (device globals: no allocation allowed)
__device__ float    g_xh[T_ * B_ * H_];    // (t*8 + b)*512   : x_t @ W_xh + b_h
__device__ float    g_hs[B_ * T_ * H_];    // (b*256 + t)*512 : hidden states (GEMM A layout)
__device__ unsigned g_flags[RNN_CTAS];

// ---------------------------------------------------------------------------
// Kernel A: xh[t][b][:] = embed[x_ids[b][t]] @ W_xh + b_h   (also zero flags)
// grid (256, 8), block 512. Each block: one t, all 8 batches, 64 output cols.
// ---------------------------------------------------------------------------
__global__ void embed_xh_kernel(const int*   __restrict__ x_ids,
                                const float* __restrict__ embed,
                                const float* __restrict__ W_xh,
                                const float* __restrict__ b_h)
{
    const int t   = blockIdx.x;
    const int jb  = blockIdx.y;
    const int tid = threadIdx.x;

    if (blockIdx.x == 0 && blockIdx.y == 0 && tid < RNN_CTAS) g_flags[tid] = 0u;

    __shared__ float x_sm[B_][E_];     // 8 KB
    __shared__ float w_sm[64][64];     // 16 KB
    __shared__ int   ids[B_];

    if (tid < B_) ids[tid] = x_ids[tid * T_ + t];
    __syncthreads();

    {   // load 8 embedding rows (8*256 floats, 4 per thread)
        int idx = tid * 4;
        int b = idx >> 8, k = idx & 255;
        float4 v = *(const float4*)(embed + (size_t)ids[b] * E_ + k);
        *(float4*)(&x_sm[b][k]) = v;
    }

    const int b   = tid >> 6;          // 0..7
    const int j   = tid & 63;
    const int col = jb * 64 + j;
    float acc = b_h[col];

    #pragma unroll
    for (int kb = 0; kb < 4; kb++) {
        __syncthreads();
        for (int idx = tid; idx < 64 * 64; idx += 512) {
            int kr = idx >> 6, jc = idx & 63;
            w_sm[kr][jc] = W_xh[(size_t)(kb * 64 + kr) * H_ + jb * 64 + jc];
        }
        __syncthreads();
        #pragma unroll 8
        for (int k = 0; k < 64; k++)
            acc = fmaf(x_sm[b][kb * 64 + k], w_sm[k][j], acc);
    }
    g_xh[(size_t)(t * B_ + b) * H_ + col] = acc;
}

// ---------------------------------------------------------------------------
// Kernel B: persistent RNN scan. 32 CTAs x 128 threads, each CTA owns 16 cols
// of W_hh (SMEM, transposed, padded). Cross-CTA sync: per-CTA monotonic flags.
// ---------------------------------------------------------------------------
__device__ __forceinline__ unsigned ld_acq(const unsigned* p) {
    unsigned v;
    asm volatile("ld.acquire.gpu.global.u32 %0, [%1];" : "=r"(v) : "l"(p) : "memory");
    return v;
}

__global__ void rnn_kernel(const float* __restrict__ W_hh)
{
    extern __shared__ float sm[];
    float* Wt  = sm;                   // [16][WT_STRIDE]  (transposed: [j][k])
    float* hsm = sm + 16 * WT_STRIDE;  // [8][512]

    const int tid = threadIdx.x;       // 0..127
    const int cta = blockIdx.x;        // 0..31
    const int b   = tid >> 4;          // 0..7
    const int j   = tid & 15;          // 0..15
    const int col = cta * 16 + j;

    // Stage this CTA's W_hh slice, transposed for per-thread float4 k-reads
    for (int idx = tid; idx < H_ * 16; idx += 128) {
        int k = idx >> 4, jj = idx & 15;
        Wt[jj * WT_STRIDE + k] = W_hh[(size_t)k * H_ + cta * 16 + jj];
    }
    __syncthreads();

    for (int t = 0; t < T_; t++) {
        float acc;
        if (t > 0) {
            // wait for all CTAs to have published h_{t-1}
            if (tid < RNN_CTAS) { while (ld_acq(&g_flags[tid]) < (unsigned)t) {} }
            __syncthreads();
            // broadcast h_{t-1} into SMEM (16 KB from L2)
            for (int i = tid; i < (B_ * H_) / 4; i += 128) {
                int bb = i >> 7, kk = (i & 127) * 4;
                *(float4*)(hsm + bb * H_ + kk) =
                    *(const float4*)(g_hs + (size_t)(bb * T_ + (t - 1)) * H_ + kk);
            }
            __syncthreads();
            float a0 = 0.f, a1 = 0.f, a2 = 0.f, a3 = 0.f;
            const float4* h4 = (const float4*)(hsm + b * H_);
            const float4* w4 = (const float4*)(Wt + j * WT_STRIDE);
            #pragma unroll 8
            for (int kq = 0; kq < H_ / 4; kq++) {
                float4 h = h4[kq]; float4 w = w4[kq];
                a0 = fmaf(h.x, w.x, a0); a1 = fmaf(h.y, w.y, a1);
                a2 = fmaf(h.z, w.z, a2); a3 = fmaf(h.w, w.w, a3);
            }
            acc = (a0 + a1) + (a2 + a3);
            __syncthreads();   // done reading hsm/Wt before anyone proceeds
        } else {
            acc = 0.f;
        }
        acc += g_xh[(size_t)(t * B_ + b) * H_ + col];
        float hn = tanhf(acc);
        g_hs[(size_t)(b * T_ + t) * H_ + col] = hn;

        __threadfence();       // make the STG visible gpu-wide (all threads)
        __syncthreads();
        if (tid == 0) atomicExch(&g_flags[cta], (unsigned)(t + 1));
    }
}

// ---------------------------------------------------------------------------
// Kernel C: Y = hs @ W_hy + b_y via tf32 mma.sync.m16n8k8 (RNA-rounded tf32).
// CTA tile 128x128, BK=16, 8 warps (4m x 2n), warp tile 32x64.
// ---------------------------------------------------------------------------
__device__ __forceinline__ uint32_t cvt_tf32(float x) {
    uint32_t r;
    asm("cvt.rna.tf32.f32 %0, %1;" : "=r"(r) : "f"(x));
    return r;
}

__device__ __forceinline__ void mma_tf32(float* c, const uint32_t* a, const uint32_t* b) {
    asm volatile(
        "mma.sync.aligned.m16n8k8.row.col.f32.tf32.tf32.f32 "
        "{%0,%1,%2,%3}, {%4,%5,%6,%7}, {%8,%9}, {%0,%1,%2,%3};\n"
        : "+f"(c[0]), "+f"(c[1]), "+f"(c[2]), "+f"(c[3])
        : "r"(a[0]), "r"(a[1]), "r"(a[2]), "r"(a[3]),
          "r"(b[0]), "r"(b[1]));
}

#define AS_STRIDE 20    // 16 + pad -> conflict-free A frag LDS
#define BS_STRIDE 136   // 128 + pad -> conflict-free B frag LDS

__global__ __launch_bounds__(256) void out_gemm_kernel(
    const float* __restrict__ W_hy,
    const float* __restrict__ b_y,
    float*       __restrict__ Y)
{
    __shared__ uint32_t As[128 * AS_STRIDE];  // 10.0 KB
    __shared__ uint32_t Bs[16 * BS_STRIDE];   //  8.5 KB

    const int tid  = threadIdx.x;
    const int n0   = blockIdx.x * 128;
    const int m0   = blockIdx.y * 128;
    const int wid  = tid >> 5, lane = tid & 31;
    const int wm   = wid & 3,  wn   = wid >> 2;   // 4 x 2 warp grid
    const int gid  = lane >> 2, tig = lane & 3;

    float acc[2][8][4];
    #pragma unroll
    for (int mt = 0; mt < 2; mt++)
        #pragma unroll
        for (int nt = 0; nt < 8; nt++)
            #pragma unroll
            for (int i = 0; i < 4; i++) acc[mt][nt][i] = 0.f;

    for (int kt = 0; kt < H_ / 16; kt++) {
        // A tile: 128 x 16 (512 float4, 2 per thread)
        #pragma unroll
        for (int i = 0; i < 2; i++) {
            int q = tid + i * 256;
            int r = q >> 2, kq = (q & 3) * 4;
            float4 v = *(const float4*)(g_hs + (size_t)(m0 + r) * H_ + kt * 16 + kq);
            uint4 u = { cvt_tf32(v.x), cvt_tf32(v.y), cvt_tf32(v.z), cvt_tf32(v.w) };
            *(uint4*)(As + r * AS_STRIDE + kq) = u;
        }
        // B tile: 16 x 128 (512 float4, 2 per thread)
        #pragma unroll
        for (int i = 0; i < 2; i++) {
            int q = tid + i * 256;
            int r = q >> 5, nq = (q & 31) * 4;
            float4 v = *(const float4*)(W_hy + (size_t)(kt * 16 + r) * V_ + n0 + nq);
            uint4 u = { cvt_tf32(v.x), cvt_tf32(v.y), cvt_tf32(v.z), cvt_tf32(v.w) };
            *(uint4*)(Bs + r * BS_STRIDE + nq) = u;
        }
        __syncthreads();

        #pragma unroll
        for (int ks = 0; ks < 2; ks++) {
            uint32_t afr[2][4], bfr[8][2];
            #pragma unroll
            for (int mt = 0; mt < 2; mt++) {
                int r = wm * 32 + mt * 16;
                afr[mt][0] = As[(r + gid)     * AS_STRIDE + ks * 8 + tig];
                afr[mt][1] = As[(r + gid + 8) * AS_STRIDE + ks * 8 + tig];
                afr[mt][2] = As[(r + gid)     * AS_STRIDE + ks * 8 + tig + 4];
                afr[mt][3] = As[(r + gid + 8) * AS_STRIDE + ks * 8 + tig + 4];
            }
            #pragma unroll
            for (int nt = 0; nt < 8; nt++) {
                int cc = wn * 64 + nt * 8 + gid;
                bfr[nt][0] = Bs[(ks * 8 + tig)     * BS_STRIDE + cc];
                bfr[nt][1] = Bs[(ks * 8 + tig + 4) * BS_STRIDE + cc];
            }
            #pragma unroll
            for (int mt = 0; mt < 2; mt++)
                #pragma unroll
                for (int nt = 0; nt < 8; nt++)
                    mma_tf32(acc[mt][nt], afr[mt], bfr[nt]);
        }
        __syncthreads();
    }

    // Epilogue: + b_y, store
    #pragma unroll
    for (int mt = 0; mt < 2; mt++) {
        int r0 = m0 + wm * 32 + mt * 16 + gid;
        #pragma unroll
        for (int nt = 0; nt < 8; nt++) {
            int c = n0 + wn * 64 + nt * 8 + tig * 2;
            float by0 = __ldg(b_y + c), by1 = __ldg(b_y + c + 1);
            float2 v0 = { acc[mt][nt][0] + by0, acc[mt][nt][1] + by1 };
            float2 v1 = { acc[mt][nt][2] + by0, acc[mt][nt][3] + by1 };
            *(float2*)(Y + (size_t)r0       * V_ + c) = v0;
            *(float2*)(Y + (size_t)(r0 + 8) * V_ + c) = v1;
        }
    }
}

// ---------------------------------------------------------------------------
extern "C" void kernel_launch(void* const* d_in, const int* in_sizes, int n_in,
                              void* d_out, int out_size)
{
    const int*   x_ids = (const int*)  d_in[0];
    const float* embed = (const float*)d_in[1];
    const float* W_xh  = (const float*)d_in[2];
    const float* b_h   = (const float*)d_in[3];
    const float* W_hh  = (const float*)d_in[4];
    const float* W_hy  = (const float*)d_in[5];
    const float* b_y   = (const float*)d_in[6];
    float* Y = (float*)d_out;

    (void)in_sizes; (void)n_in; (void)out_size;

    cudaFuncSetAttribute(rnn_kernel,
                         cudaFuncAttributeMaxDynamicSharedMemorySize, RNN_SMEM);

    embed_xh_kernel<<<dim3(T_, 8), 512>>>(x_ids, embed, W_xh, b_h);
    rnn_kernel<<<RNN_CTAS, 128, RNN_SMEM>>>(W_hh);
    out_gemm_kernel<<<dim3(V_ / 128, (B_ * T_) / 128), 256>>>(W_hy, b_y, Y);
}

// round 3
// speedup vs baseline: 1.4979x; 1.4979x over previous
#include <cuda_runtime.h>
#include <cstdint>
#include <cstddef>

#define B_ 8
#define T_ 256
#define V_ 32000
#define E_ 256
#define H_ 512

// ---------------------------------------------------------------------------
// Scratch (device globals: no allocation allowed)
// ---------------------------------------------------------------------------
__device__ float    g_xh[T_ * B_ * H_];    // (t*8 + b)*512   : x_t @ W_xh + b_h
__device__ float    g_hs[B_ * T_ * H_];    // (b*256 + t)*512 : hidden states (GEMM A layout)
__device__ unsigned g_count;               // epoch counter for RNN cross-CTA sync

// ===========================================================================
// Kernel A: xh[m][:] = embed[id(m)] @ W_xh + b_h, m = t*8+b.
// Gather-GEMM: grid (8 nblk, 16 mblk) x 256 thr, tile 128x64, BK=16.
// Also resets g_count for this replay.
// ===========================================================================
__global__ __launch_bounds__(256) void embed_xh_kernel(
    const int*   __restrict__ x_ids,
    const float* __restrict__ embed,
    const float* __restrict__ W_xh,
    const float* __restrict__ b_h)
{
    if (blockIdx.x == 0 && blockIdx.y == 0 && threadIdx.x == 0) g_count = 0u;

    __shared__ float Asm[128][17];
    __shared__ float Bsm[16][68];
    __shared__ int   ids_sm[128];

    const int tid = threadIdx.x;
    const int n0  = blockIdx.x * 64;
    const int m0  = blockIdx.y * 128;

    if (tid < 128) {
        int m = m0 + tid;                       // m = t*8 + b
        ids_sm[tid] = x_ids[(m & 7) * T_ + (m >> 3)];
    }
    __syncthreads();

    const int tx = tid & 15;                    // 16 col groups of 4
    const int ty = tid >> 4;                    // 16 row groups of 8

    float acc[8][4];
    #pragma unroll
    for (int c = 0; c < 4; c++) {
        float bv = b_h[n0 + tx * 4 + c];
        #pragma unroll
        for (int i = 0; i < 8; i++) acc[i][c] = bv;
    }

    for (int kt = 0; kt < E_ / 16; kt++) {
        // A tile 128x16 (gathered embedding rows): 512 float4, 2/thread
        #pragma unroll
        for (int i = 0; i < 2; i++) {
            int idx = tid + i * 256;
            int r = idx >> 2, kq = (idx & 3) * 4;
            float4 v = *(const float4*)(embed + (size_t)ids_sm[r] * E_ + kt * 16 + kq);
            Asm[r][kq] = v.x; Asm[r][kq+1] = v.y; Asm[r][kq+2] = v.z; Asm[r][kq+3] = v.w;
        }
        // B tile 16x64: 256 float4, 1/thread
        {
            int r = tid >> 4, nq = (tid & 15) * 4;
            float4 v = *(const float4*)(W_xh + (size_t)(kt * 16 + r) * H_ + n0 + nq);
            Bsm[r][nq] = v.x; Bsm[r][nq+1] = v.y; Bsm[r][nq+2] = v.z; Bsm[r][nq+3] = v.w;
        }
        __syncthreads();

        #pragma unroll
        for (int k = 0; k < 16; k++) {
            float4 bv = *(const float4*)(&Bsm[k][tx * 4]);
            #pragma unroll
            for (int i = 0; i < 8; i++) {
                float av = Asm[ty * 8 + i][k];
                acc[i][0] = fmaf(av, bv.x, acc[i][0]);
                acc[i][1] = fmaf(av, bv.y, acc[i][1]);
                acc[i][2] = fmaf(av, bv.z, acc[i][2]);
                acc[i][3] = fmaf(av, bv.w, acc[i][3]);
            }
        }
        __syncthreads();
    }

    #pragma unroll
    for (int i = 0; i < 8; i++) {
        int m = m0 + ty * 8 + i;
        float4 v = { acc[i][0], acc[i][1], acc[i][2], acc[i][3] };
        *(float4*)(g_xh + (size_t)m * H_ + n0 + tx * 4) = v;
    }
}

// ===========================================================================
// Kernel B: persistent RNN scan. 64 CTAs x 128 threads, 8 cols per CTA.
// k-split by 2 with shfl reduce. Epoch-counter sync (release-add / acquire).
// SMEM half-split layouts are conflict-free for the compute loop.
// ===========================================================================
#define RNN_CTAS 64
#define WT_ROW 520      // 8 rows; k-halves at +0 / +260
#define H_ROW  528      // 8 rows; k-halves at +0 / +264

__device__ __forceinline__ unsigned ld_acq(const unsigned* p) {
    unsigned v;
    asm volatile("ld.acquire.gpu.global.u32 %0, [%1];" : "=r"(v) : "l"(p) : "memory");
    return v;
}
__device__ __forceinline__ void red_add_release(unsigned* p, unsigned v) {
    asm volatile("red.release.gpu.global.add.u32 [%0], %1;" :: "l"(p), "r"(v) : "memory");
}

__global__ __launch_bounds__(128) void rnn_kernel(const float* __restrict__ W_hh)
{
    __shared__ float Wt[8 * WT_ROW];
    __shared__ float hsm[B_ * H_ROW];

    const int tid = threadIdx.x;       // 0..127
    const int cta = blockIdx.x;        // 0..63
    const int b   = tid >> 4;          // 0..7
    const int j   = (tid >> 1) & 7;    // 0..7
    const int ks  = tid & 1;           // k-half
    const int col = cta * 8 + j;

    // Stage W_hh slice, transposed, k-halves split for bank-conflict freedom
    for (int idx = tid; idx < H_ * 8; idx += 128) {
        int k = idx >> 3, jj = idx & 7;
        int off = (k < 256) ? k : k + 4;
        Wt[jj * WT_ROW + off] = W_hh[(size_t)k * H_ + cta * 8 + jj];
    }
    __syncthreads();

    for (int t = 0; t < T_; t++) {
        // prefetch xh early (independent of h)
        float xh = g_xh[(size_t)(t * B_ + b) * H_ + col];

        float acc = 0.f;
        if (t > 0) {
            if (tid == 0) {
                unsigned tgt = (unsigned)(RNN_CTAS * t);
                while (ld_acq(&g_count) < tgt) __nanosleep(32);
            }
            __syncthreads();
            // broadcast h_{t-1} into SMEM (half-split layout)
            for (int i = tid; i < (B_ * H_) / 4; i += 128) {
                int bb = i >> 7, kk = (i & 127) * 4;
                int off = (kk < 256) ? kk : kk + 8;
                *(float4*)(hsm + bb * H_ROW + off) =
                    *(const float4*)(g_hs + (size_t)(bb * T_ + (t - 1)) * H_ + kk);
            }
            __syncthreads();

            float a0 = 0.f, a1 = 0.f, a2 = 0.f, a3 = 0.f;
            const float4* h4 = (const float4*)(hsm + b * H_ROW + ks * 264);
            const float4* w4 = (const float4*)(Wt + j * WT_ROW + ks * 260);
            #pragma unroll 8
            for (int kq = 0; kq < 64; kq++) {
                float4 h = h4[kq]; float4 w = w4[kq];
                a0 = fmaf(h.x, w.x, a0); a1 = fmaf(h.y, w.y, a1);
                a2 = fmaf(h.z, w.z, a2); a3 = fmaf(h.w, w.w, a3);
            }
            acc = (a0 + a1) + (a2 + a3);
            acc += __shfl_xor_sync(0xffffffffu, acc, 1);
        }
        float hn = tanhf(acc + xh);
        if (ks == 0)
            g_hs[(size_t)(b * T_ + t) * H_ + col] = hn;

        __syncthreads();                       // all stores done CTA-wide
        if (tid == 0) red_add_release(&g_count, 1u);
    }
}

// ===========================================================================
// Kernel C: Y = hs @ W_hy + b_y. tf32 mma.sync m16n8k8, RNA rounding at
// fragment load. 4-stage cp.async pipeline. CTA tile 128x128, BK=16,
// 8 warps (4m x 2n), warp tile 32x64. grid (16 mblk fastest, 250 nblk).
// ===========================================================================
#define STAGES 4
#define AS_ST 20                       // 16 + pad (floats)
#define BS_ST 136                      // 128 + pad (floats)
#define A_STAGE (128 * AS_ST)
#define B_STAGE (16 * BS_ST)
#define GEMM_SMEM ((A_STAGE + B_STAGE) * STAGES * 4)   // 75776 B

__device__ __forceinline__ void cp_async16(float* dst, const float* src) {
    uint32_t s = (uint32_t)__cvta_generic_to_shared(dst);
    asm volatile("cp.async.cg.shared.global [%0], [%1], 16;\n" :: "r"(s), "l"(src));
}
__device__ __forceinline__ uint32_t cvt_tf32(float x) {
    uint32_t r;
    asm("cvt.rna.tf32.f32 %0, %1;" : "=r"(r) : "f"(x));
    return r;
}
__device__ __forceinline__ void mma_tf32(float* c, const uint32_t* a, const uint32_t* b) {
    asm volatile(
        "mma.sync.aligned.m16n8k8.row.col.f32.tf32.tf32.f32 "
        "{%0,%1,%2,%3}, {%4,%5,%6,%7}, {%8,%9}, {%0,%1,%2,%3};\n"
        : "+f"(c[0]), "+f"(c[1]), "+f"(c[2]), "+f"(c[3])
        : "r"(a[0]), "r"(a[1]), "r"(a[2]), "r"(a[3]),
          "r"(b[0]), "r"(b[1]));
}

__global__ __launch_bounds__(256, 2) void out_gemm_kernel(
    const float* __restrict__ W_hy,
    const float* __restrict__ b_y,
    float*       __restrict__ Y)
{
    extern __shared__ float smem[];
    float* As = smem;                          // [STAGES][A_STAGE]
    float* Bs = smem + STAGES * A_STAGE;       // [STAGES][B_STAGE]

    const int tid  = threadIdx.x;
    const int m0   = blockIdx.x * 128;         // m fastest -> W_hy streams once
    const int n0   = blockIdx.y * 128;
    const int wid  = tid >> 5, lane = tid & 31;
    const int wm   = wid & 3,  wn   = wid >> 2;
    const int gid  = lane >> 2, tig = lane & 3;

    float acc[2][8][4];
    #pragma unroll
    for (int mt = 0; mt < 2; mt++)
        #pragma unroll
        for (int nt = 0; nt < 8; nt++)
            #pragma unroll
            for (int i = 0; i < 4; i++) acc[mt][nt][i] = 0.f;

    // stage loader
    auto load_stage = [&](int slot, int kt) {
        #pragma unroll
        for (int i = 0; i < 2; i++) {
            int idx = tid + i * 256;
            int r = idx >> 2, kq = (idx & 3) * 4;
            cp_async16(As + slot * A_STAGE + r * AS_ST + kq,
                       g_hs + (size_t)(m0 + r) * H_ + kt * 16 + kq);
        }
        #pragma unroll
        for (int i = 0; i < 2; i++) {
            int idx = tid + i * 256;
            int r = idx >> 5, nq = (idx & 31) * 4;
            cp_async16(Bs + slot * B_STAGE + r * BS_ST + nq,
                       W_hy + (size_t)(kt * 16 + r) * V_ + n0 + nq);
        }
    };

    #pragma unroll
    for (int s = 0; s < STAGES - 1; s++) {
        load_stage(s, s);
        asm volatile("cp.async.commit_group;\n" ::: "memory");
    }

    for (int kt = 0; kt < H_ / 16; kt++) {
        asm volatile("cp.async.wait_group 2;\n" ::: "memory");
        __syncthreads();

        int nk = kt + STAGES - 1;
        if (nk < H_ / 16) load_stage(nk & (STAGES - 1), nk);
        asm volatile("cp.async.commit_group;\n" ::: "memory");

        const float* Af = As + (kt & (STAGES - 1)) * A_STAGE;
        const float* Bf = Bs + (kt & (STAGES - 1)) * B_STAGE;

        #pragma unroll
        for (int ksf = 0; ksf < 2; ksf++) {
            uint32_t afr[2][4], bfr[8][2];
            #pragma unroll
            for (int mt = 0; mt < 2; mt++) {
                int r = wm * 32 + mt * 16;
                afr[mt][0] = cvt_tf32(Af[(r + gid)     * AS_ST + ksf * 8 + tig]);
                afr[mt][1] = cvt_tf32(Af[(r + gid + 8) * AS_ST + ksf * 8 + tig]);
                afr[mt][2] = cvt_tf32(Af[(r + gid)     * AS_ST + ksf * 8 + tig + 4]);
                afr[mt][3] = cvt_tf32(Af[(r + gid + 8) * AS_ST + ksf * 8 + tig + 4]);
            }
            #pragma unroll
            for (int nt = 0; nt < 8; nt++) {
                int cc = wn * 64 + nt * 8 + gid;
                bfr[nt][0] = cvt_tf32(Bf[(ksf * 8 + tig)     * BS_ST + cc]);
                bfr[nt][1] = cvt_tf32(Bf[(ksf * 8 + tig + 4) * BS_ST + cc]);
            }
            #pragma unroll
            for (int mt = 0; mt < 2; mt++)
                #pragma unroll
                for (int nt = 0; nt < 8; nt++)
                    mma_tf32(acc[mt][nt], afr[mt], bfr[nt]);
        }
    }

    // Epilogue: + b_y, store
    #pragma unroll
    for (int mt = 0; mt < 2; mt++) {
        int r0 = m0 + wm * 32 + mt * 16 + gid;
        #pragma unroll
        for (int nt = 0; nt < 8; nt++) {
            int c = n0 + wn * 64 + nt * 8 + tig * 2;
            float by0 = __ldg(b_y + c), by1 = __ldg(b_y + c + 1);
            float2 v0 = { acc[mt][nt][0] + by0, acc[mt][nt][1] + by1 };
            float2 v1 = { acc[mt][nt][2] + by0, acc[mt][nt][3] + by1 };
            *(float2*)(Y + (size_t)r0       * V_ + c) = v0;
            *(float2*)(Y + (size_t)(r0 + 8) * V_ + c) = v1;
        }
    }
}

// ---------------------------------------------------------------------------
extern "C" void kernel_launch(void* const* d_in, const int* in_sizes, int n_in,
                              void* d_out, int out_size)
{
    const int*   x_ids = (const int*)  d_in[0];
    const float* embed = (const float*)d_in[1];
    const float* W_xh  = (const float*)d_in[2];
    const float* b_h   = (const float*)d_in[3];
    const float* W_hh  = (const float*)d_in[4];
    const float* W_hy  = (const float*)d_in[5];
    const float* b_y   = (const float*)d_in[6];
    float* Y = (float*)d_out;

    (void)in_sizes; (void)n_in; (void)out_size;

    static int init_done = 0;
    if (!init_done) {
        cudaFuncSetAttribute(out_gemm_kernel,
                             cudaFuncAttributeMaxDynamicSharedMemorySize, GEMM_SMEM);
        init_done = 1;
    }

    embed_xh_kernel<<<dim3(8, 16), 256>>>(x_ids, embed, W_xh, b_h);
    rnn_kernel<<<RNN_CTAS, 128>>>(W_hh);
    out_gemm_kernel<<<dim3((B_ * T_) / 128, V_ / 128), 256, GEMM_SMEM>>>(W_hy, b_y, Y);
}